// round 3
// baseline (speedup 1.0000x reference)
#include <cuda_runtime.h>

// RoIPool: feature_map [B=2, H=50, W=50, C=256] f32, rpn_pred [B=2, N=128, 4] f32
// out [B, N, 7, 7, C] f32.
//   x1=(int)(W*p0); y1=(int)(H*p1); x2=(int)(W*p2); y2=(int)(H*p3)
//   sw=(x2-x1)/7; sh=(y2-y1)/7   (>=1 by input construction, <=4)
//   out[b,n,i,j,c] = max_{r<sh,t<sw} fm[b, y1+i*sh+r, x1+j*sw+t, c]
// Bounds: x1+7*sw-1 <= x2-1 <= 49 (same for y) -> reference clip is dead code.
//
// CTA = (i, n, b): one bin-ROW per CTA. Each thread owns 4 channels and all 7
// j-bins -> ~44 independent in-flight LDG.128 per thread (deep MLP), ROI math
// amortized 7x, j-invariant (r,t) predicates batch 7 loads per branch.

#define POOL 7
#define NROIS 128
#define BB 2
#define HH 50
#define WW 50
#define CC 256
#define C4 (CC / 4)   // 64 float4 per pixel

__global__ __launch_bounds__(64) void roi_pool_kernel(
    const float4* __restrict__ fm,     // [B*H*W*C4] float4
    const float*  __restrict__ rois,   // [B*N*4]
    float4*       __restrict__ out)    // [B*N*49*C4] float4
{
    const int i  = blockIdx.x;         // pooled row 0..6
    const int n  = blockIdx.y;         // roi
    const int b  = blockIdx.z;         // batch
    const int c4 = threadIdx.x;        // 0..63 -> 4 channels

    const float* p = rois + ((b * NROIS + n) << 2);
    const int x1 = (int)(WW * __ldg(p + 0));
    const int y1 = (int)(HH * __ldg(p + 1));
    const int x2 = (int)(WW * __ldg(p + 2));
    const int y2 = (int)(HH * __ldg(p + 3));
    const int sw = (x2 - x1) / POOL;   // in [1,4]
    const int sh = (y2 - y1) / POOL;   // in [1,4]

    const int row0 = y1 + i * sh;
    // Base pointer at (row0, x1); bin j starts at column offset j*sw.
    const float4* base = fm + ((b * HH + row0) * WW + x1) * C4 + c4;

    // Per-bin column offsets (in float4 units), hoisted out of the (r,t) loops.
    int colOff[POOL];
    #pragma unroll
    for (int j = 0; j < POOL; ++j) colOff[j] = j * sw * C4;

    // (r=0,t=0) cell is always valid for every bin: init the 7 maxima from it.
    float4 m[POOL];
    #pragma unroll
    for (int j = 0; j < POOL; ++j) m[j] = __ldg(base + colOff[j]);

    #pragma unroll
    for (int r = 0; r < 4; ++r) {
        const float4* rbase = base + r * (WW * C4);
        #pragma unroll
        for (int t = 0; t < 4; ++t) {
            if (r == 0 && t == 0) continue;
            if ((r < sh) & (t < sw)) {
                #pragma unroll
                for (int j = 0; j < POOL; ++j) {
                    const float4 v = __ldg(rbase + colOff[j] + t * C4);
                    m[j].x = fmaxf(m[j].x, v.x);
                    m[j].y = fmaxf(m[j].y, v.y);
                    m[j].z = fmaxf(m[j].z, v.z);
                    m[j].w = fmaxf(m[j].w, v.w);
                }
            }
        }
    }

    // out[b, n, i, j, c4] — coalesced across the warp for each j.
    float4* obase = out + (((b * NROIS + n) * POOL + i) * POOL) * C4 + c4;
    #pragma unroll
    for (int j = 0; j < POOL; ++j) obase[j * C4] = m[j];
}

extern "C" void kernel_launch(void* const* d_in, const int* in_sizes, int n_in,
                              void* d_out, int out_size) {
    const float4* fm   = (const float4*)d_in[0];  // feature_map
    const float*  rois = (const float*)d_in[1];   // rpn_pred
    float4*       out  = (float4*)d_out;

    dim3 grid(POOL, NROIS, BB);
    roi_pool_kernel<<<grid, 64>>>(fm, rois, out);
}

// round 4
// speedup vs baseline: 1.1785x; 1.1785x over previous
#include <cuda_runtime.h>

// RoIPool: feature_map [B=2, H=50, W=50, C=256] f32, rpn_pred [B=2, N=128, 4] f32
// out [B, N, 7, 7, C] f32.
//   x1=(int)(W*p0); y1=(int)(H*p1); x2=(int)(W*p2); y2=(int)(H*p3)
//   sw=(x2-x1)/7; sh=(y2-y1)/7   (in [1,4] by input construction)
//   out[b,n,i,j,c] = max_{r<sh,t<sw} fm[b, y1+i*sh+r, x1+j*sw+t, c]
// Bounds: x1+7*sw-1 <= x2-1 <= 49 (same for y) -> reference clip is dead code.
//
// CTA = (bin-pair, n, b): 64 threads, each thread owns 4 channels of TWO
// consecutive bins. ROI read as one LDG.128 (shortest dependent chain head);
// (r,t) predicates shared by both bins -> paired independent loads per branch.

#define POOL 7
#define NROIS 128
#define BB 2
#define HH 50
#define WW 50
#define CC 256
#define C4 (CC / 4)   // 64 float4 per pixel
#define NBINS (POOL * POOL)       // 49
#define NPAIR ((NBINS + 1) / 2)   // 25

__global__ __launch_bounds__(64) void roi_pool_kernel(
    const float4* __restrict__ fm,     // [B*H*W*C4] float4
    const float4* __restrict__ rois,   // [B*N] float4 (x1,y1,x2,y2)
    float4*       __restrict__ out)    // [B*N*49*C4] float4
{
    const int pb = blockIdx.x;         // 0..24 bin pair
    const int n  = blockIdx.y;         // roi
    const int b  = blockIdx.z;         // batch
    const int c4 = threadIdx.x;        // 0..63 -> 4 channels

    const int bin0 = pb * 2;
    const int bin1 = bin0 + 1;
    const bool has1 = (bin1 < NBINS);

    // Single 128-bit ROI load.
    const float4 rp = __ldg(rois + b * NROIS + n);
    const int x1 = (int)(WW * rp.x);
    const int y1 = (int)(HH * rp.y);
    const int x2 = (int)(WW * rp.z);
    const int y2 = (int)(HH * rp.w);
    const int sw = (x2 - x1) / POOL;   // in [1,4]
    const int sh = (y2 - y1) / POOL;   // in [1,4]

    const int i0 = bin0 / POOL, j0 = bin0 - i0 * POOL;
    const int i1 = bin1 / POOL, j1 = bin1 - i1 * POOL;

    const float4* fmb = fm + (b * HH * WW) * C4 + c4;
    const float4* base0 = fmb + ((y1 + i0 * sh) * WW + (x1 + j0 * sw)) * C4;
    // For bin 49 (invalid), alias base1 to base0 so speculative loads are safe.
    const float4* base1 = has1
        ? fmb + ((y1 + i1 * sh) * WW + (x1 + j1 * sw)) * C4
        : base0;

    // (0,0) always valid: init maxima from it (two independent loads).
    float4 m0 = __ldg(base0);
    float4 m1 = __ldg(base1);

    #pragma unroll
    for (int r = 0; r < 4; ++r) {
        #pragma unroll
        for (int t = 0; t < 4; ++t) {
            if (r == 0 && t == 0) continue;
            if ((r < sh) & (t < sw)) {
                const int off = (r * WW + t) * C4;
                const float4 v0 = __ldg(base0 + off);
                const float4 v1 = __ldg(base1 + off);
                m0.x = fmaxf(m0.x, v0.x);
                m0.y = fmaxf(m0.y, v0.y);
                m0.z = fmaxf(m0.z, v0.z);
                m0.w = fmaxf(m0.w, v0.w);
                m1.x = fmaxf(m1.x, v1.x);
                m1.y = fmaxf(m1.y, v1.y);
                m1.z = fmaxf(m1.z, v1.z);
                m1.w = fmaxf(m1.w, v1.w);
            }
        }
    }

    float4* obase = out + ((b * NROIS + n) * NBINS + bin0) * C4 + c4;
    obase[0] = m0;
    if (has1) obase[C4] = m1;
}

extern "C" void kernel_launch(void* const* d_in, const int* in_sizes, int n_in,
                              void* d_out, int out_size) {
    const float4* fm   = (const float4*)d_in[0];  // feature_map
    const float4* rois = (const float4*)d_in[1];  // rpn_pred as float4
    float4*       out  = (float4*)d_out;

    dim3 grid(NPAIR, NROIS, BB);
    roi_pool_kernel<<<grid, 64>>>(fm, rois, out);
}